// round 7
// baseline (speedup 1.0000x reference)
#include <cuda_runtime.h>
#include <cuda_bf16.h>
#include <cuda_fp16.h>

#define NMAX 50000
#define EMAX 800000
#define GRAPHS 64
#define SCAN_B 1024

// ---------------- device scratch (allocation-free rule) ----------------
static __device__ __half g_h0[NMAX * 64];   // layer-1 output, fp16
static __device__ __half g_h1[NMAX * 128];  // layer-2 output, fp16
static __device__ float g_dinv[NMAX];
static __device__ int   g_cnt[NMAX];
static __device__ int   g_rowptr[NMAX + 1];
static __device__ int   g_cursor[NMAX];
static __device__ int   g_bsum[64];
static __device__ int   g_esrc[EMAX];       // CSR src, grouped by dst
static __device__ float g_enorm[EMAX];      // per-edge norm, same order
static __device__ float g_psum[GRAPHS * 128];
static __device__ float g_pcnt[GRAPHS];

typedef unsigned long long ull;

// ---------------- f32x2 helpers ----------------
__device__ __forceinline__ ull pack2(float x, float y) {
    ull r; asm("mov.b64 %0, {%1,%2};" : "=l"(r) : "f"(x), "f"(y)); return r;
}
__device__ __forceinline__ void unpack2(ull v, float& x, float& y) {
    asm("mov.b64 {%0,%1}, %2;" : "=f"(x), "=f"(y) : "l"(v));
}
__device__ __forceinline__ ull ffma2(ull a, ull b, ull c) {
    ull d; asm("fma.rn.f32x2 %0, %1, %2, %3;" : "=l"(d) : "l"(a), "l"(b), "l"(c));
    return d;
}

// ---------------- prep ----------------
__global__ void k_zero(int n) {
    int i = blockIdx.x * blockDim.x + threadIdx.x;
    if (i < n) g_cnt[i] = 0;
    if (i < GRAPHS * 128) g_psum[i] = 0.0f;
    if (i < GRAPHS) g_pcnt[i] = 0.0f;
}

// degree histogram + graph-size histogram (batch) in one pass
__global__ void k_count(const int* __restrict__ dst, const int* __restrict__ batch,
                        int E, int n) {
    int e = blockIdx.x * blockDim.x + threadIdx.x;
    if (e < E) atomicAdd(&g_cnt[dst[e]], 1);
    if (e < n) atomicAdd(&g_pcnt[batch[e]], 1.0f);
}

// Phase A: per-block exclusive scan of g_cnt -> g_rowptr (local) + block totals.
__global__ void k_scanA(int n) {
    __shared__ int swarp[32];
    int t = threadIdx.x;            // 1024
    int i = blockIdx.x * SCAN_B + t;
    int lane = t & 31, wid = t >> 5;
    int v = (i < n) ? g_cnt[i] : 0;
    if (i < n) g_dinv[i] = rsqrtf((float)v + 1.0f);
    int incl = v;
#pragma unroll
    for (int off = 1; off < 32; off <<= 1) {
        int y = __shfl_up_sync(0xffffffffu, incl, off);
        if (lane >= off) incl += y;
    }
    if (lane == 31) swarp[wid] = incl;
    __syncthreads();
    if (wid == 0) {
        int w = swarp[lane];
#pragma unroll
        for (int off = 1; off < 32; off <<= 1) {
            int y = __shfl_up_sync(0xffffffffu, w, off);
            if (lane >= off) w += y;
        }
        swarp[lane] = w;
    }
    __syncthreads();
    int excl = incl - v + ((wid > 0) ? swarp[wid - 1] : 0);
    if (i < n) g_rowptr[i] = excl;
    if (t == SCAN_B - 1) g_bsum[blockIdx.x] = excl + v;
}

// Phase C: two-warp shfl scan of the <=64 block totals (parallel, in-block),
// then add offsets, zero cursor, finalize rowptr[n].
__global__ void k_scanC(int n, int E, int nb) {
    __shared__ int pref[64];
    __shared__ int wtot;
    int tid = threadIdx.x;
    if (tid < 64) {
        int lane = tid & 31;
        int v = (tid < nb) ? g_bsum[tid] : 0;
        int incl = v;
#pragma unroll
        for (int off = 1; off < 32; off <<= 1) {
            int y = __shfl_up_sync(0xffffffffu, incl, off);
            if (lane >= off) incl += y;
        }
        pref[tid] = incl - v;
        if (tid == 31) wtot = incl;
    }
    __syncthreads();
    if (tid >= 32 && tid < 64) pref[tid] += wtot;
    __syncthreads();
    int i = blockIdx.x * blockDim.x + threadIdx.x;
    if (i < n) {
        g_rowptr[i] += pref[i >> 10];
        g_cursor[i] = 0;
    }
    if (i == 0) g_rowptr[n] = E;
}

__global__ void k_fill(const int* __restrict__ src, const int* __restrict__ dst, int E) {
    int e = blockIdx.x * blockDim.x + threadIdx.x;
    if (e < E) {
        int s = src[e], d = dst[e];
        int pos = g_rowptr[d] + atomicAdd(&g_cursor[d], 1);
        g_esrc[pos] = s;
        g_enorm[pos] = g_dinv[s] * g_dinv[d];
    }
}

// ---------------- Layer 1 fused: agg(C=3) + 3->64 GEMM + relu -> g_h0 -------
__global__ void __launch_bounds__(256) k_layer1(const float* __restrict__ x,
                                                const float* __restrict__ W,
                                                const float* __restrict__ b, int n) {
    const int NPB = 64;
    __shared__ float sa[NPB][3];
    __shared__ float sW[192];
    __shared__ float sb[64];
    int tid = threadIdx.x, wid = tid >> 5, lane = tid & 31;
    int node0 = blockIdx.x * NPB;
    if (tid < 192) sW[tid] = W[tid];
    if (tid < 64) sb[tid] = b[tid];

    for (int k = 0; k < NPB; k += 8) {
        int lr = k + wid;
        int i = node0 + lr;
        if (i < n) {
            int beg = g_rowptr[i], end = g_rowptr[i + 1];
            float a0 = 0.f, a1 = 0.f, a2 = 0.f;
            for (int j = beg + lane; j < end; j += 32) {
                int s = g_esrc[j];
                float w = g_enorm[j];
                a0 += x[s * 3 + 0] * w;
                a1 += x[s * 3 + 1] * w;
                a2 += x[s * 3 + 2] * w;
            }
#pragma unroll
            for (int off = 16; off > 0; off >>= 1) {
                a0 += __shfl_down_sync(0xffffffffu, a0, off);
                a1 += __shfl_down_sync(0xffffffffu, a1, off);
                a2 += __shfl_down_sync(0xffffffffu, a2, off);
            }
            if (lane == 0) {
                float di = g_dinv[i], sw = di * di;
                sa[lr][0] = a0 + x[i * 3 + 0] * sw;
                sa[lr][1] = a1 + x[i * 3 + 1] * sw;
                sa[lr][2] = a2 + x[i * 3 + 2] * sw;
            }
        }
    }
    __syncthreads();

    int tc = tid & 63, ty = tid >> 6;
    float w0 = sW[tc], w1 = sW[64 + tc], w2 = sW[128 + tc], bb = sb[tc];
#pragma unroll 4
    for (int r = 0; r < 16; r++) {
        int lr = ty * 16 + r;
        int row = node0 + lr;
        if (row >= n) break;
        float v = bb + sa[lr][0] * w0 + sa[lr][1] * w1 + sa[lr][2] * w2;
        g_h0[row * 64 + tc] = __float2half(fmaxf(v, 0.0f));
    }
}

// ---------------- Fused layer: agg(K) + KxC GEMM (+relu) -------------------
// K in {64,128}, C=128. Block: 512 thr, 32 nodes/tile, grid-stride over tiles
// (W stays hot in L1 across a block's tiles).
// Phase A: warp aggregates 2 nodes (VPL=K/32 fp16/lane) into smem (fp32).
// Phase B: tc=0..63 (2 cols), ty=0..7 (4 rows each), f32x2 accum.
template <int K, int VPL, bool POOL>
__global__ void __launch_bounds__(512) k_layer(const float* __restrict__ W,
                                               const float* __restrict__ b,
                                               const int* __restrict__ batch,
                                               int n, int ntiles) {
    const int C = 128, ROWS = 32;
    __shared__ float sh[ROWS][K];
    int tid = threadIdx.x, wid = tid >> 5, lane = tid & 31;
    const __half* __restrict__ hp = (K == 64) ? g_h0 : g_h1;
    int tc = tid & 63, ty = tid >> 6;  // ty 0..7, 4 rows each
    const ull* __restrict__ Wll = (const ull*)W;
    float2 bb = *(const float2*)&b[2 * tc];
    ull binit = pack2(bb.x, bb.y);

    for (int tile = blockIdx.x; tile < ntiles; tile += gridDim.x) {
        int row0 = tile * ROWS;

#pragma unroll
        for (int rr = 0; rr < 2; rr++) {
            int lr = wid * 2 + rr;
            int i = row0 + lr;
            if (i < n) {
                int beg = g_rowptr[i], end = g_rowptr[i + 1];
                float di = g_dinv[i], sw = di * di;
                float acc[VPL];
                if (VPL == 4) {
                    uint2 u = *(const uint2*)(hp + (size_t)i * K + lane * 4);
                    float2 f0 = __half22float2(*reinterpret_cast<__half2*>(&u.x));
                    float2 f1 = __half22float2(*reinterpret_cast<__half2*>(&u.y));
                    acc[0] = f0.x * sw; acc[1] = f0.y * sw; acc[2] = f1.x * sw; acc[3] = f1.y * sw;
                } else {
                    unsigned u = *(const unsigned*)(hp + (size_t)i * K + lane * 2);
                    float2 f0 = __half22float2(*reinterpret_cast<__half2*>(&u));
                    acc[0] = f0.x * sw; acc[1] = f0.y * sw;
                }
                int j = beg;
                for (; j + 4 <= end; j += 4) {
                    int s0 = g_esrc[j], s1 = g_esrc[j + 1];
                    int s2 = g_esrc[j + 2], s3 = g_esrc[j + 3];
                    float w0 = g_enorm[j], w1 = g_enorm[j + 1];
                    float w2 = g_enorm[j + 2], w3 = g_enorm[j + 3];
                    if (VPL == 4) {
                        uint2 u0 = *(const uint2*)(hp + (size_t)s0 * K + lane * 4);
                        uint2 u1 = *(const uint2*)(hp + (size_t)s1 * K + lane * 4);
                        uint2 u2 = *(const uint2*)(hp + (size_t)s2 * K + lane * 4);
                        uint2 u3 = *(const uint2*)(hp + (size_t)s3 * K + lane * 4);
                        float2 a0 = __half22float2(*reinterpret_cast<__half2*>(&u0.x));
                        float2 b0 = __half22float2(*reinterpret_cast<__half2*>(&u0.y));
                        float2 a1 = __half22float2(*reinterpret_cast<__half2*>(&u1.x));
                        float2 b1 = __half22float2(*reinterpret_cast<__half2*>(&u1.y));
                        float2 a2 = __half22float2(*reinterpret_cast<__half2*>(&u2.x));
                        float2 b2 = __half22float2(*reinterpret_cast<__half2*>(&u2.y));
                        float2 a3 = __half22float2(*reinterpret_cast<__half2*>(&u3.x));
                        float2 b3 = __half22float2(*reinterpret_cast<__half2*>(&u3.y));
                        acc[0] += a0.x * w0 + a1.x * w1 + a2.x * w2 + a3.x * w3;
                        acc[1] += a0.y * w0 + a1.y * w1 + a2.y * w2 + a3.y * w3;
                        acc[2] += b0.x * w0 + b1.x * w1 + b2.x * w2 + b3.x * w3;
                        acc[3] += b0.y * w0 + b1.y * w1 + b2.y * w2 + b3.y * w3;
                    } else {
                        unsigned u0 = *(const unsigned*)(hp + (size_t)s0 * K + lane * 2);
                        unsigned u1 = *(const unsigned*)(hp + (size_t)s1 * K + lane * 2);
                        unsigned u2 = *(const unsigned*)(hp + (size_t)s2 * K + lane * 2);
                        unsigned u3 = *(const unsigned*)(hp + (size_t)s3 * K + lane * 2);
                        float2 a0 = __half22float2(*reinterpret_cast<__half2*>(&u0));
                        float2 a1 = __half22float2(*reinterpret_cast<__half2*>(&u1));
                        float2 a2 = __half22float2(*reinterpret_cast<__half2*>(&u2));
                        float2 a3 = __half22float2(*reinterpret_cast<__half2*>(&u3));
                        acc[0] += a0.x * w0 + a1.x * w1 + a2.x * w2 + a3.x * w3;
                        acc[1] += a0.y * w0 + a1.y * w1 + a2.y * w2 + a3.y * w3;
                    }
                }
                for (; j < end; j++) {
                    int s = g_esrc[j];
                    float w = g_enorm[j];
                    if (VPL == 4) {
                        uint2 u = *(const uint2*)(hp + (size_t)s * K + lane * 4);
                        float2 f0 = __half22float2(*reinterpret_cast<__half2*>(&u.x));
                        float2 f1 = __half22float2(*reinterpret_cast<__half2*>(&u.y));
                        acc[0] += f0.x * w; acc[1] += f0.y * w;
                        acc[2] += f1.x * w; acc[3] += f1.y * w;
                    } else {
                        unsigned u = *(const unsigned*)(hp + (size_t)s * K + lane * 2);
                        float2 f0 = __half22float2(*reinterpret_cast<__half2*>(&u));
                        acc[0] += f0.x * w; acc[1] += f0.y * w;
                    }
                }
#pragma unroll
                for (int v = 0; v < VPL; v++) sh[lr][lane * VPL + v] = acc[v];
            }
        }
        __syncthreads();

        // Phase B: GEMM from smem
        ull acc[4];
#pragma unroll
        for (int r = 0; r < 4; r++) acc[r] = binit;
        int rbase = ty * 4;
#pragma unroll 4
        for (int k = 0; k < K; k += 2) {
            ull w0 = Wll[k * (C / 2) + tc];
            ull w1 = Wll[(k + 1) * (C / 2) + tc];
#pragma unroll
            for (int r = 0; r < 4; r++) {
                float2 s2 = *(const float2*)&sh[rbase + r][k];
                acc[r] = ffma2(pack2(s2.x, s2.x), w0, acc[r]);
                acc[r] = ffma2(pack2(s2.y, s2.y), w1, acc[r]);
            }
        }

        if (!POOL) {
#pragma unroll
            for (int r = 0; r < 4; r++) {
                int row = row0 + rbase + r;
                if (row < n) {
                    float xv, yv; unpack2(acc[r], xv, yv);
                    __half2 o = __floats2half2_rn(fmaxf(xv, 0.0f), fmaxf(yv, 0.0f));
                    *(__half2*)&g_h1[(size_t)row * C + 2 * tc] = o;
                }
            }
        } else {
            int curg = -1;
            float rx = 0.0f, ry = 0.0f;
#pragma unroll
            for (int r = 0; r < 4; r++) {
                int row = row0 + rbase + r;
                if (row >= n) break;
                float xv, yv; unpack2(acc[r], xv, yv);
                xv = fmaxf(xv, 0.0f); yv = fmaxf(yv, 0.0f);
                int g = __ldg(&batch[row]);
                if (g != curg) {
                    if (curg >= 0) {
                        atomicAdd(&g_psum[curg * 128 + 2 * tc], rx);
                        atomicAdd(&g_psum[curg * 128 + 2 * tc + 1], ry);
                    }
                    curg = g; rx = 0.0f; ry = 0.0f;
                }
                rx += xv; ry += yv;
            }
            if (curg >= 0) {
                atomicAdd(&g_psum[curg * 128 + 2 * tc], rx);
                atomicAdd(&g_psum[curg * 128 + 2 * tc + 1], ry);
            }
        }
        __syncthreads();  // protect sh before next tile's phase A
    }
}

// ---------------- MLP head ----------------
__global__ void k_fc(const float* __restrict__ Wf1, const float* __restrict__ bf1,
                     const float* __restrict__ Wf2, const float* __restrict__ bf2,
                     float* __restrict__ out) {
    int g = blockIdx.x;
    int t = threadIdx.x;  // 128
    __shared__ float p[128];
    __shared__ float f1[64];
    float inv = 1.0f / fmaxf(g_pcnt[g], 1.0f);
    p[t] = g_psum[g * 128 + t] * inv;
    __syncthreads();
    if (t < 64) {
        float acc = bf1[t];
#pragma unroll
        for (int k = 0; k < 128; k++) acc += p[k] * Wf1[k * 64 + t];
        f1[t] = fmaxf(acc, 0.0f);
    }
    __syncthreads();
    if (t < 10) {
        float acc = bf2[t];
#pragma unroll
        for (int k = 0; k < 64; k++) acc += f1[k] * Wf2[k * 10 + t];
        out[g * 10 + t] = acc;
    }
}

extern "C" void kernel_launch(void* const* d_in, const int* in_sizes, int n_in,
                              void* d_out, int out_size) {
    const float* x   = (const float*)d_in[0];
    const int* ei    = (const int*)d_in[1];
    const int* batch = (const int*)d_in[2];
    const float* W1  = (const float*)d_in[3];
    const float* b1  = (const float*)d_in[4];
    const float* W2  = (const float*)d_in[5];
    const float* b2  = (const float*)d_in[6];
    const float* W3  = (const float*)d_in[7];
    const float* b3  = (const float*)d_in[8];
    const float* Wf1 = (const float*)d_in[9];
    const float* bf1 = (const float*)d_in[10];
    const float* Wf2 = (const float*)d_in[11];
    const float* bf2 = (const float*)d_in[12];
    float* out = (float*)d_out;

    int N = in_sizes[0] / 3;
    int E = in_sizes[1] / 2;
    const int* src = ei;
    const int* dst = ei + E;
    int NB = (N + SCAN_B - 1) / SCAN_B;

    // CSR + norms (once per launch, reused by all 3 layers)
    k_zero<<<(N + 255) / 256, 256>>>(N);
    k_count<<<(E + 255) / 256, 256>>>(dst, batch, E, N);
    k_scanA<<<NB, SCAN_B>>>(N);
    k_scanC<<<(N + 255) / 256, 256>>>(N, E, NB);
    k_fill<<<(E + 255) / 256, 256>>>(src, dst, E);

    // Fused layers
    int ntiles = (N + 31) / 32;
    int nblk = ntiles < 592 ? ntiles : 592;  // 148 SMs x 4 blocks
    k_layer1<<<(N + 63) / 64, 256>>>(x, W1, b1, N);
    k_layer<64, 2, false><<<nblk, 512>>>(W2, b2, batch, N, ntiles);
    k_layer<128, 4, true><<<nblk, 512>>>(W3, b3, batch, N, ntiles);

    // Head
    k_fc<<<GRAPHS, 128>>>(Wf1, bf1, Wf2, bf2, out);
}

// round 8
// speedup vs baseline: 1.1377x; 1.1377x over previous
#include <cuda_runtime.h>
#include <cuda_bf16.h>
#include <cuda_fp16.h>

#define NMAX 50000
#define EMAX 800000
#define GRAPHS 64
#define SCAN_B 1024

// ---------------- device scratch (allocation-free rule) ----------------
static __device__ __half g_h0[NMAX * 64];   // layer-1 output, fp16
static __device__ __half g_h1[NMAX * 128];  // layer-2 output, fp16
static __device__ float g_dinv[NMAX];
static __device__ int   g_cnt[NMAX];
static __device__ int   g_rowptr[NMAX + 1];
static __device__ int   g_cursor[NMAX];
static __device__ int   g_bsum[64];
static __device__ int   g_sync;             // grid-sync counter for k_scan
static __device__ int   g_esrc[EMAX];       // CSR src, grouped by dst
static __device__ float g_enorm[EMAX];      // per-edge norm, same order
static __device__ float g_psum[GRAPHS * 128];
static __device__ float g_pcnt[GRAPHS];

typedef unsigned long long ull;

// ---------------- f32x2 helpers ----------------
__device__ __forceinline__ ull pack2(float x, float y) {
    ull r; asm("mov.b64 %0, {%1,%2};" : "=l"(r) : "f"(x), "f"(y)); return r;
}
__device__ __forceinline__ void unpack2(ull v, float& x, float& y) {
    asm("mov.b64 {%0,%1}, %2;" : "=f"(x), "=f"(y) : "l"(v));
}
__device__ __forceinline__ ull ffma2(ull a, ull b, ull c) {
    ull d; asm("fma.rn.f32x2 %0, %1, %2, %3;" : "=l"(d) : "l"(a), "l"(b), "l"(c));
    return d;
}

// ---------------- prep ----------------
__global__ void k_zero(int n) {
    int i = blockIdx.x * blockDim.x + threadIdx.x;
    if (i < n) g_cnt[i] = 0;
    if (i < GRAPHS * 128) g_psum[i] = 0.0f;
    if (i < GRAPHS) g_pcnt[i] = 0.0f;
    if (i == 0) g_sync = 0;
}

// degree histogram + graph-size histogram (batch) in one pass
__global__ void k_count(const int* __restrict__ dst, const int* __restrict__ batch,
                        int E, int n) {
    int e = blockIdx.x * blockDim.x + threadIdx.x;
    if (e < E) atomicAdd(&g_cnt[dst[e]], 1);
    if (e < n) atomicAdd(&g_pcnt[batch[e]], 1.0f);
}

// Merged scan: per-block local scan -> publish totals -> spin grid-sync ->
// every block prefixes the <=49 totals -> final rowptr/cursor write.
// gridDim.x <= 49 blocks of 1024: single wave on 148 SMs, deadlock-free.
__global__ void __launch_bounds__(1024) k_scan(int n, int E) {
    __shared__ int swarp[32];
    __shared__ int pref[64];
    __shared__ int wtot;
    int t = threadIdx.x;
    int i = blockIdx.x * SCAN_B + t;
    int lane = t & 31, wid = t >> 5;
    int nb = gridDim.x;

    int v = (i < n) ? g_cnt[i] : 0;
    if (i < n) g_dinv[i] = rsqrtf((float)v + 1.0f);
    int incl = v;
#pragma unroll
    for (int off = 1; off < 32; off <<= 1) {
        int y = __shfl_up_sync(0xffffffffu, incl, off);
        if (lane >= off) incl += y;
    }
    if (lane == 31) swarp[wid] = incl;
    __syncthreads();
    if (wid == 0) {
        int w = swarp[lane];
#pragma unroll
        for (int off = 1; off < 32; off <<= 1) {
            int y = __shfl_up_sync(0xffffffffu, w, off);
            if (lane >= off) w += y;
        }
        swarp[lane] = w;
    }
    __syncthreads();
    int excl = incl - v + ((wid > 0) ? swarp[wid - 1] : 0);

    // publish block total, grid-sync
    if (t == SCAN_B - 1) g_bsum[blockIdx.x] = excl + v;
    __threadfence();
    __syncthreads();
    if (t == 0) {
        atomicAdd(&g_sync, 1);
        while (atomicAdd(&g_sync, 0) < nb) { }
    }
    __syncthreads();

    // all blocks redundantly prefix the block totals (<=64)
    if (t < 64) {
        int bv = (t < nb) ? g_bsum[t] : 0;
        int binc = bv;
#pragma unroll
        for (int off = 1; off < 32; off <<= 1) {
            int y = __shfl_up_sync(0xffffffffu, binc, off);
            if (lane >= off) binc += y;
        }
        pref[t] = binc - bv;
        if (t == 31) wtot = binc;
    }
    __syncthreads();
    if (t >= 32 && t < 64) pref[t] += wtot;
    __syncthreads();

    int base = pref[blockIdx.x];
    if (i < n) {
        int rp = excl + base;
        g_rowptr[i] = rp;
        g_cursor[i] = 0;
    }
    if (i == 0) g_rowptr[n] = E;
}

__global__ void k_fill(const int* __restrict__ src, const int* __restrict__ dst, int E) {
    int e = blockIdx.x * blockDim.x + threadIdx.x;
    if (e < E) {
        int s = src[e], d = dst[e];
        int pos = g_rowptr[d] + atomicAdd(&g_cursor[d], 1);
        g_esrc[pos] = s;
        g_enorm[pos] = g_dinv[s] * g_dinv[d];
    }
}

// ---------------- Layer 1 fused: agg(C=3) + 3->64 GEMM + relu -> g_h0 -------
__global__ void __launch_bounds__(256) k_layer1(const float* __restrict__ x,
                                                const float* __restrict__ W,
                                                const float* __restrict__ b, int n) {
    const int NPB = 64;
    __shared__ float sa[NPB][3];
    __shared__ float sW[192];
    __shared__ float sb[64];
    int tid = threadIdx.x, wid = tid >> 5, lane = tid & 31;
    int node0 = blockIdx.x * NPB;
    if (tid < 192) sW[tid] = W[tid];
    if (tid < 64) sb[tid] = b[tid];

    for (int k = 0; k < NPB; k += 8) {
        int lr = k + wid;
        int i = node0 + lr;
        if (i < n) {
            int beg = g_rowptr[i], end = g_rowptr[i + 1];
            float a0 = 0.f, a1 = 0.f, a2 = 0.f;
            for (int j = beg + lane; j < end; j += 32) {
                int s = g_esrc[j];
                float w = g_enorm[j];
                a0 += x[s * 3 + 0] * w;
                a1 += x[s * 3 + 1] * w;
                a2 += x[s * 3 + 2] * w;
            }
#pragma unroll
            for (int off = 16; off > 0; off >>= 1) {
                a0 += __shfl_down_sync(0xffffffffu, a0, off);
                a1 += __shfl_down_sync(0xffffffffu, a1, off);
                a2 += __shfl_down_sync(0xffffffffu, a2, off);
            }
            if (lane == 0) {
                float di = g_dinv[i], sw = di * di;
                sa[lr][0] = a0 + x[i * 3 + 0] * sw;
                sa[lr][1] = a1 + x[i * 3 + 1] * sw;
                sa[lr][2] = a2 + x[i * 3 + 2] * sw;
            }
        }
    }
    __syncthreads();

    int tc = tid & 63, ty = tid >> 6;
    float w0 = sW[tc], w1 = sW[64 + tc], w2 = sW[128 + tc], bb = sb[tc];
#pragma unroll 4
    for (int r = 0; r < 16; r++) {
        int lr = ty * 16 + r;
        int row = node0 + lr;
        if (row >= n) break;
        float v = bb + sa[lr][0] * w0 + sa[lr][1] * w1 + sa[lr][2] * w2;
        g_h0[row * 64 + tc] = __float2half(fmaxf(v, 0.0f));
    }
}

// ---------------- Fused layer: agg(K) + KxC GEMM (+relu) -------------------
// K in {64,128}, C=128. Block: 256 thr, 16 nodes. (R6 structure — proven.)
template <int K, int VPL, bool POOL>
__global__ void __launch_bounds__(256) k_layer(const float* __restrict__ W,
                                               const float* __restrict__ b,
                                               const int* __restrict__ batch, int n) {
    const int C = 128, ROWS = 16;
    __shared__ float sh[ROWS][K];
    int tid = threadIdx.x, wid = tid >> 5, lane = tid & 31;
    int row0 = blockIdx.x * ROWS;
    const __half* __restrict__ hp = (K == 64) ? g_h0 : g_h1;

#pragma unroll
    for (int rr = 0; rr < 2; rr++) {
        int lr = wid * 2 + rr;
        int i = row0 + lr;
        if (i < n) {
            int beg = g_rowptr[i], end = g_rowptr[i + 1];
            float di = g_dinv[i], sw = di * di;
            float acc[VPL];
            if (VPL == 4) {
                uint2 u = *(const uint2*)(hp + (size_t)i * K + lane * 4);
                float2 f0 = __half22float2(*reinterpret_cast<__half2*>(&u.x));
                float2 f1 = __half22float2(*reinterpret_cast<__half2*>(&u.y));
                acc[0] = f0.x * sw; acc[1] = f0.y * sw; acc[2] = f1.x * sw; acc[3] = f1.y * sw;
            } else {
                unsigned u = *(const unsigned*)(hp + (size_t)i * K + lane * 2);
                float2 f0 = __half22float2(*reinterpret_cast<__half2*>(&u));
                acc[0] = f0.x * sw; acc[1] = f0.y * sw;
            }
            int j = beg;
            for (; j + 4 <= end; j += 4) {
                int s0 = g_esrc[j], s1 = g_esrc[j + 1], s2 = g_esrc[j + 2], s3 = g_esrc[j + 3];
                float w0 = g_enorm[j], w1 = g_enorm[j + 1];
                float w2 = g_enorm[j + 2], w3 = g_enorm[j + 3];
                if (VPL == 4) {
                    uint2 u0 = *(const uint2*)(hp + (size_t)s0 * K + lane * 4);
                    uint2 u1 = *(const uint2*)(hp + (size_t)s1 * K + lane * 4);
                    uint2 u2 = *(const uint2*)(hp + (size_t)s2 * K + lane * 4);
                    uint2 u3 = *(const uint2*)(hp + (size_t)s3 * K + lane * 4);
                    float2 a0 = __half22float2(*reinterpret_cast<__half2*>(&u0.x));
                    float2 b0 = __half22float2(*reinterpret_cast<__half2*>(&u0.y));
                    float2 a1 = __half22float2(*reinterpret_cast<__half2*>(&u1.x));
                    float2 b1 = __half22float2(*reinterpret_cast<__half2*>(&u1.y));
                    float2 a2 = __half22float2(*reinterpret_cast<__half2*>(&u2.x));
                    float2 b2 = __half22float2(*reinterpret_cast<__half2*>(&u2.y));
                    float2 a3 = __half22float2(*reinterpret_cast<__half2*>(&u3.x));
                    float2 b3 = __half22float2(*reinterpret_cast<__half2*>(&u3.y));
                    acc[0] += a0.x * w0 + a1.x * w1 + a2.x * w2 + a3.x * w3;
                    acc[1] += a0.y * w0 + a1.y * w1 + a2.y * w2 + a3.y * w3;
                    acc[2] += b0.x * w0 + b1.x * w1 + b2.x * w2 + b3.x * w3;
                    acc[3] += b0.y * w0 + b1.y * w1 + b2.y * w2 + b3.y * w3;
                } else {
                    unsigned u0 = *(const unsigned*)(hp + (size_t)s0 * K + lane * 2);
                    unsigned u1 = *(const unsigned*)(hp + (size_t)s1 * K + lane * 2);
                    unsigned u2 = *(const unsigned*)(hp + (size_t)s2 * K + lane * 2);
                    unsigned u3 = *(const unsigned*)(hp + (size_t)s3 * K + lane * 2);
                    float2 a0 = __half22float2(*reinterpret_cast<__half2*>(&u0));
                    float2 a1 = __half22float2(*reinterpret_cast<__half2*>(&u1));
                    float2 a2 = __half22float2(*reinterpret_cast<__half2*>(&u2));
                    float2 a3 = __half22float2(*reinterpret_cast<__half2*>(&u3));
                    acc[0] += a0.x * w0 + a1.x * w1 + a2.x * w2 + a3.x * w3;
                    acc[1] += a0.y * w0 + a1.y * w1 + a2.y * w2 + a3.y * w3;
                }
            }
            for (; j < end; j++) {
                int s = g_esrc[j];
                float w = g_enorm[j];
                if (VPL == 4) {
                    uint2 u = *(const uint2*)(hp + (size_t)s * K + lane * 4);
                    float2 f0 = __half22float2(*reinterpret_cast<__half2*>(&u.x));
                    float2 f1 = __half22float2(*reinterpret_cast<__half2*>(&u.y));
                    acc[0] += f0.x * w; acc[1] += f0.y * w; acc[2] += f1.x * w; acc[3] += f1.y * w;
                } else {
                    unsigned u = *(const unsigned*)(hp + (size_t)s * K + lane * 2);
                    float2 f0 = __half22float2(*reinterpret_cast<__half2*>(&u));
                    acc[0] += f0.x * w; acc[1] += f0.y * w;
                }
            }
#pragma unroll
            for (int v = 0; v < VPL; v++) sh[lr][lane * VPL + v] = acc[v];
        }
    }
    __syncthreads();

    // Phase B: GEMM from smem
    int tc = tid & 63, ty = tid >> 6;  // ty 0..3, 4 rows each
    const ull* __restrict__ Wll = (const ull*)W;
    ull acc[4];
    {
        float2 bb = *(const float2*)&b[2 * tc];
        ull binit = pack2(bb.x, bb.y);
#pragma unroll
        for (int r = 0; r < 4; r++) acc[r] = binit;
    }
    int rbase = ty * 4;
#pragma unroll 4
    for (int k = 0; k < K; k += 2) {
        ull w0 = Wll[k * (C / 2) + tc];
        ull w1 = Wll[(k + 1) * (C / 2) + tc];
#pragma unroll
        for (int r = 0; r < 4; r++) {
            float2 s2 = *(const float2*)&sh[rbase + r][k];
            acc[r] = ffma2(pack2(s2.x, s2.x), w0, acc[r]);
            acc[r] = ffma2(pack2(s2.y, s2.y), w1, acc[r]);
        }
    }

    if (!POOL) {
#pragma unroll
        for (int r = 0; r < 4; r++) {
            int row = row0 + rbase + r;
            if (row < n) {
                float xv, yv; unpack2(acc[r], xv, yv);
                __half2 o = __floats2half2_rn(fmaxf(xv, 0.0f), fmaxf(yv, 0.0f));
                *(__half2*)&g_h1[(size_t)row * C + 2 * tc] = o;
            }
        }
    } else {
        int curg = -1;
        float rx = 0.0f, ry = 0.0f;
#pragma unroll
        for (int r = 0; r < 4; r++) {
            int row = row0 + rbase + r;
            if (row >= n) break;
            float xv, yv; unpack2(acc[r], xv, yv);
            xv = fmaxf(xv, 0.0f); yv = fmaxf(yv, 0.0f);
            int g = __ldg(&batch[row]);
            if (g != curg) {
                if (curg >= 0) {
                    atomicAdd(&g_psum[curg * 128 + 2 * tc], rx);
                    atomicAdd(&g_psum[curg * 128 + 2 * tc + 1], ry);
                }
                curg = g; rx = 0.0f; ry = 0.0f;
            }
            rx += xv; ry += yv;
        }
        if (curg >= 0) {
            atomicAdd(&g_psum[curg * 128 + 2 * tc], rx);
            atomicAdd(&g_psum[curg * 128 + 2 * tc + 1], ry);
        }
    }
}

// ---------------- MLP head ----------------
__global__ void k_fc(const float* __restrict__ Wf1, const float* __restrict__ bf1,
                     const float* __restrict__ Wf2, const float* __restrict__ bf2,
                     float* __restrict__ out) {
    int g = blockIdx.x;
    int t = threadIdx.x;  // 128
    __shared__ float p[128];
    __shared__ float f1[64];
    float inv = 1.0f / fmaxf(g_pcnt[g], 1.0f);
    p[t] = g_psum[g * 128 + t] * inv;
    __syncthreads();
    if (t < 64) {
        float acc = bf1[t];
#pragma unroll
        for (int k = 0; k < 128; k++) acc += p[k] * Wf1[k * 64 + t];
        f1[t] = fmaxf(acc, 0.0f);
    }
    __syncthreads();
    if (t < 10) {
        float acc = bf2[t];
#pragma unroll
        for (int k = 0; k < 64; k++) acc += f1[k] * Wf2[k * 10 + t];
        out[g * 10 + t] = acc;
    }
}

extern "C" void kernel_launch(void* const* d_in, const int* in_sizes, int n_in,
                              void* d_out, int out_size) {
    const float* x   = (const float*)d_in[0];
    const int* ei    = (const int*)d_in[1];
    const int* batch = (const int*)d_in[2];
    const float* W1  = (const float*)d_in[3];
    const float* b1  = (const float*)d_in[4];
    const float* W2  = (const float*)d_in[5];
    const float* b2  = (const float*)d_in[6];
    const float* W3  = (const float*)d_in[7];
    const float* b3  = (const float*)d_in[8];
    const float* Wf1 = (const float*)d_in[9];
    const float* bf1 = (const float*)d_in[10];
    const float* Wf2 = (const float*)d_in[11];
    const float* bf2 = (const float*)d_in[12];
    float* out = (float*)d_out;

    int N = in_sizes[0] / 3;
    int E = in_sizes[1] / 2;
    const int* src = ei;
    const int* dst = ei + E;
    int NB = (N + SCAN_B - 1) / SCAN_B;  // <= 49

    // CSR + norms (once per launch, reused by all 3 layers)
    k_zero<<<(N + 255) / 256, 256>>>(N);
    k_count<<<(E + 255) / 256, 256>>>(dst, batch, E, N);
    k_scan<<<NB, SCAN_B>>>(N, E);
    k_fill<<<(E + 255) / 256, 256>>>(src, dst, E);

    // Fused layers (R6 config)
    k_layer1<<<(N + 63) / 64, 256>>>(x, W1, b1, N);
    k_layer<64, 2, false><<<(N + 15) / 16, 256>>>(W2, b2, batch, N);
    k_layer<128, 4, true><<<(N + 15) / 16, 256>>>(W3, b3, batch, N);

    // Head
    k_fc<<<GRAPHS, 128>>>(Wf1, bf1, Wf2, bf2, out);
}

// round 9
// speedup vs baseline: 1.1453x; 1.0067x over previous
#include <cuda_runtime.h>
#include <cuda_bf16.h>
#include <cuda_fp16.h>

#define NMAX 50000
#define EMAX 800000
#define GRAPHS 64
#define SCAN_B 1024

// ---------------- device scratch (allocation-free rule) ----------------
static __device__ __half g_h0[NMAX * 64];   // layer-1 output, fp16
static __device__ __half g_h1[NMAX * 128];  // layer-2 output, fp16
static __device__ float g_dinv[NMAX];
static __device__ int   g_cnt[NMAX];
static __device__ int   g_rowptr[NMAX + 1];
static __device__ int   g_cursor[NMAX];
static __device__ int   g_bsum[64];
static __device__ int   g_sync;             // spin barrier (zeroed by k_zero)
static __device__ unsigned long long g_edge[EMAX];  // packed {norm<<32 | src}
static __device__ float g_psum[GRAPHS * 128];
static __device__ float g_pcnt[GRAPHS];

typedef unsigned long long ull;

// ---------------- f32x2 helpers ----------------
__device__ __forceinline__ ull pack2(float x, float y) {
    ull r; asm("mov.b64 %0, {%1,%2};" : "=l"(r) : "f"(x), "f"(y)); return r;
}
__device__ __forceinline__ void unpack2(ull v, float& x, float& y) {
    asm("mov.b64 {%0,%1}, %2;" : "=f"(x), "=f"(y) : "l"(v));
}
__device__ __forceinline__ ull ffma2(ull a, ull b, ull c) {
    ull d; asm("fma.rn.f32x2 %0, %1, %2, %3;" : "=l"(d) : "l"(a), "l"(b), "l"(c));
    return d;
}

// unpack edge record
__device__ __forceinline__ void eunpack(ull r, int& s, float& w) {
    s = (int)(unsigned)r;
    w = __uint_as_float((unsigned)(r >> 32));
}

// ---------------- prep ----------------
__global__ void k_zero(int n) {
    int i = blockIdx.x * blockDim.x + threadIdx.x;
    if (i < n) g_cnt[i] = 0;
    if (i < GRAPHS * 128) g_psum[i] = 0.0f;
    if (i < GRAPHS) g_pcnt[i] = 0.0f;
    if (i == 0) g_sync = 0;
}

// Single-wave CSR builder: count -> scan -> fill, with spin grid barriers.
// gridDim.x <= 49 blocks of 1024: single wave on 148 SMs, deadlock-free.
__global__ void __launch_bounds__(1024) k_prep(const int* __restrict__ src,
                                               const int* __restrict__ dst,
                                               const int* __restrict__ batch,
                                               int n, int E) {
    __shared__ int swarp[32];
    __shared__ int pref[64];
    __shared__ int wtot;
    int t = threadIdx.x;
    int lane = t & 31, wid = t >> 5;
    int nb = gridDim.x;
    int gtid = blockIdx.x * SCAN_B + t;
    int nthr = nb * SCAN_B;

    // ---- phase 1: histograms ----
    for (int e = gtid; e < E; e += nthr) atomicAdd(&g_cnt[dst[e]], 1);
    for (int i = gtid; i < n; i += nthr) atomicAdd(&g_pcnt[batch[i]], 1.0f);

    // barrier -> g_sync == nb
    __threadfence();
    __syncthreads();
    if (t == 0) {
        atomicAdd(&g_sync, 1);
        while (atomicAdd(&g_sync, 0) < nb) { }
    }
    __syncthreads();

    // ---- phase 2: local scan + dinv ----
    int i = gtid;
    int v = (i < n) ? g_cnt[i] : 0;
    if (i < n) g_dinv[i] = rsqrtf((float)v + 1.0f);
    int incl = v;
#pragma unroll
    for (int off = 1; off < 32; off <<= 1) {
        int y = __shfl_up_sync(0xffffffffu, incl, off);
        if (lane >= off) incl += y;
    }
    if (lane == 31) swarp[wid] = incl;
    __syncthreads();
    if (wid == 0) {
        int w = swarp[lane];
#pragma unroll
        for (int off = 1; off < 32; off <<= 1) {
            int y = __shfl_up_sync(0xffffffffu, w, off);
            if (lane >= off) w += y;
        }
        swarp[lane] = w;
    }
    __syncthreads();
    int excl = incl - v + ((wid > 0) ? swarp[wid - 1] : 0);
    if (t == SCAN_B - 1) g_bsum[blockIdx.x] = excl + v;

    // barrier -> g_sync == 2*nb
    __threadfence();
    __syncthreads();
    if (t == 0) {
        atomicAdd(&g_sync, 1);
        while (atomicAdd(&g_sync, 0) < 2 * nb) { }
    }
    __syncthreads();

    // ---- phase 3: prefix block totals, write rowptr/cursor ----
    if (t < 64) {
        int bv = (t < nb) ? g_bsum[t] : 0;
        int binc = bv;
#pragma unroll
        for (int off = 1; off < 32; off <<= 1) {
            int y = __shfl_up_sync(0xffffffffu, binc, off);
            if (lane >= off) binc += y;
        }
        pref[t] = binc - bv;
        if (t == 31) wtot = binc;
    }
    __syncthreads();
    if (t >= 32 && t < 64) pref[t] += wtot;
    __syncthreads();
    if (i < n) {
        int rp = excl + pref[blockIdx.x];
        g_rowptr[i] = rp;
        g_cursor[i] = rp;
    }
    if (gtid == 0) g_rowptr[n] = E;

    // barrier -> g_sync == 3*nb
    __threadfence();
    __syncthreads();
    if (t == 0) {
        atomicAdd(&g_sync, 1);
        while (atomicAdd(&g_sync, 0) < 3 * nb) { }
    }
    __syncthreads();

    // ---- phase 4: fill packed edge records ----
    for (int e = gtid; e < E; e += nthr) {
        int s = src[e], d = dst[e];
        int pos = atomicAdd(&g_cursor[d], 1);
        float nm = g_dinv[s] * g_dinv[d];
        g_edge[pos] = ((ull)__float_as_uint(nm) << 32) | (unsigned)s;
    }
}

// ---------------- Layer 1 fused: agg(C=3) + 3->64 GEMM + relu -> g_h0 -------
__global__ void __launch_bounds__(256) k_layer1(const float* __restrict__ x,
                                                const float* __restrict__ W,
                                                const float* __restrict__ b, int n) {
    const int NPB = 64;
    __shared__ float sa[NPB][3];
    __shared__ float sW[192];
    __shared__ float sb[64];
    int tid = threadIdx.x, wid = tid >> 5, lane = tid & 31;
    int node0 = blockIdx.x * NPB;
    if (tid < 192) sW[tid] = W[tid];
    if (tid < 64) sb[tid] = b[tid];

    for (int k = 0; k < NPB; k += 8) {
        int lr = k + wid;
        int i = node0 + lr;
        if (i < n) {
            int beg = g_rowptr[i], end = g_rowptr[i + 1];
            float a0 = 0.f, a1 = 0.f, a2 = 0.f;
            for (int j = beg + lane; j < end; j += 32) {
                int s; float w; eunpack(g_edge[j], s, w);
                a0 += x[s * 3 + 0] * w;
                a1 += x[s * 3 + 1] * w;
                a2 += x[s * 3 + 2] * w;
            }
#pragma unroll
            for (int off = 16; off > 0; off >>= 1) {
                a0 += __shfl_down_sync(0xffffffffu, a0, off);
                a1 += __shfl_down_sync(0xffffffffu, a1, off);
                a2 += __shfl_down_sync(0xffffffffu, a2, off);
            }
            if (lane == 0) {
                float di = g_dinv[i], sw = di * di;
                sa[lr][0] = a0 + x[i * 3 + 0] * sw;
                sa[lr][1] = a1 + x[i * 3 + 1] * sw;
                sa[lr][2] = a2 + x[i * 3 + 2] * sw;
            }
        }
    }
    __syncthreads();

    int tc = tid & 63, ty = tid >> 6;
    float w0 = sW[tc], w1 = sW[64 + tc], w2 = sW[128 + tc], bb = sb[tc];
#pragma unroll 4
    for (int r = 0; r < 16; r++) {
        int lr = ty * 16 + r;
        int row = node0 + lr;
        if (row >= n) break;
        float v = bb + sa[lr][0] * w0 + sa[lr][1] * w1 + sa[lr][2] * w2;
        g_h0[row * 64 + tc] = __float2half(fmaxf(v, 0.0f));
    }
}

// ---------------- Fused layer: agg(K) + KxC GEMM (+relu) -------------------
// K in {64,128}, C=128. Block: 256 thr, 16 nodes. (R6/R8 proven structure.)
template <int K, int VPL, bool POOL>
__global__ void __launch_bounds__(256) k_layer(const float* __restrict__ W,
                                               const float* __restrict__ b,
                                               const int* __restrict__ batch, int n) {
    const int C = 128, ROWS = 16;
    __shared__ float sh[ROWS][K];
    int tid = threadIdx.x, wid = tid >> 5, lane = tid & 31;
    int row0 = blockIdx.x * ROWS;
    const __half* __restrict__ hp = (K == 64) ? g_h0 : g_h1;

#pragma unroll
    for (int rr = 0; rr < 2; rr++) {
        int lr = wid * 2 + rr;
        int i = row0 + lr;
        if (i < n) {
            int beg = g_rowptr[i], end = g_rowptr[i + 1];
            float di = g_dinv[i], sw = di * di;
            float acc[VPL];
            if (VPL == 4) {
                uint2 u = *(const uint2*)(hp + (size_t)i * K + lane * 4);
                float2 f0 = __half22float2(*reinterpret_cast<__half2*>(&u.x));
                float2 f1 = __half22float2(*reinterpret_cast<__half2*>(&u.y));
                acc[0] = f0.x * sw; acc[1] = f0.y * sw; acc[2] = f1.x * sw; acc[3] = f1.y * sw;
            } else {
                unsigned u = *(const unsigned*)(hp + (size_t)i * K + lane * 2);
                float2 f0 = __half22float2(*reinterpret_cast<__half2*>(&u));
                acc[0] = f0.x * sw; acc[1] = f0.y * sw;
            }
            int j = beg;
            for (; j + 4 <= end; j += 4) {
                int s0, s1, s2, s3; float w0, w1, w2, w3;
                eunpack(g_edge[j], s0, w0);
                eunpack(g_edge[j + 1], s1, w1);
                eunpack(g_edge[j + 2], s2, w2);
                eunpack(g_edge[j + 3], s3, w3);
                if (VPL == 4) {
                    uint2 u0 = *(const uint2*)(hp + (size_t)s0 * K + lane * 4);
                    uint2 u1 = *(const uint2*)(hp + (size_t)s1 * K + lane * 4);
                    uint2 u2 = *(const uint2*)(hp + (size_t)s2 * K + lane * 4);
                    uint2 u3 = *(const uint2*)(hp + (size_t)s3 * K + lane * 4);
                    float2 a0 = __half22float2(*reinterpret_cast<__half2*>(&u0.x));
                    float2 b0 = __half22float2(*reinterpret_cast<__half2*>(&u0.y));
                    float2 a1 = __half22float2(*reinterpret_cast<__half2*>(&u1.x));
                    float2 b1 = __half22float2(*reinterpret_cast<__half2*>(&u1.y));
                    float2 a2 = __half22float2(*reinterpret_cast<__half2*>(&u2.x));
                    float2 b2 = __half22float2(*reinterpret_cast<__half2*>(&u2.y));
                    float2 a3 = __half22float2(*reinterpret_cast<__half2*>(&u3.x));
                    float2 b3 = __half22float2(*reinterpret_cast<__half2*>(&u3.y));
                    acc[0] += a0.x * w0 + a1.x * w1 + a2.x * w2 + a3.x * w3;
                    acc[1] += a0.y * w0 + a1.y * w1 + a2.y * w2 + a3.y * w3;
                    acc[2] += b0.x * w0 + b1.x * w1 + b2.x * w2 + b3.x * w3;
                    acc[3] += b0.y * w0 + b1.y * w1 + b2.y * w2 + b3.y * w3;
                } else {
                    unsigned u0 = *(const unsigned*)(hp + (size_t)s0 * K + lane * 2);
                    unsigned u1 = *(const unsigned*)(hp + (size_t)s1 * K + lane * 2);
                    unsigned u2 = *(const unsigned*)(hp + (size_t)s2 * K + lane * 2);
                    unsigned u3 = *(const unsigned*)(hp + (size_t)s3 * K + lane * 2);
                    float2 a0 = __half22float2(*reinterpret_cast<__half2*>(&u0));
                    float2 a1 = __half22float2(*reinterpret_cast<__half2*>(&u1));
                    float2 a2 = __half22float2(*reinterpret_cast<__half2*>(&u2));
                    float2 a3 = __half22float2(*reinterpret_cast<__half2*>(&u3));
                    acc[0] += a0.x * w0 + a1.x * w1 + a2.x * w2 + a3.x * w3;
                    acc[1] += a0.y * w0 + a1.y * w1 + a2.y * w2 + a3.y * w3;
                }
            }
            for (; j < end; j++) {
                int s; float w; eunpack(g_edge[j], s, w);
                if (VPL == 4) {
                    uint2 u = *(const uint2*)(hp + (size_t)s * K + lane * 4);
                    float2 f0 = __half22float2(*reinterpret_cast<__half2*>(&u.x));
                    float2 f1 = __half22float2(*reinterpret_cast<__half2*>(&u.y));
                    acc[0] += f0.x * w; acc[1] += f0.y * w; acc[2] += f1.x * w; acc[3] += f1.y * w;
                } else {
                    unsigned u = *(const unsigned*)(hp + (size_t)s * K + lane * 2);
                    float2 f0 = __half22float2(*reinterpret_cast<__half2*>(&u));
                    acc[0] += f0.x * w; acc[1] += f0.y * w;
                }
            }
#pragma unroll
            for (int v = 0; v < VPL; v++) sh[lr][lane * VPL + v] = acc[v];
        }
    }
    __syncthreads();

    // Phase B: GEMM from smem
    int tc = tid & 63, ty = tid >> 6;  // ty 0..3, 4 rows each
    const ull* __restrict__ Wll = (const ull*)W;
    ull acc[4];
    {
        float2 bb = *(const float2*)&b[2 * tc];
        ull binit = pack2(bb.x, bb.y);
#pragma unroll
        for (int r = 0; r < 4; r++) acc[r] = binit;
    }
    int rbase = ty * 4;
#pragma unroll 4
    for (int k = 0; k < K; k += 2) {
        ull w0 = Wll[k * (C / 2) + tc];
        ull w1 = Wll[(k + 1) * (C / 2) + tc];
#pragma unroll
        for (int r = 0; r < 4; r++) {
            float2 s2 = *(const float2*)&sh[rbase + r][k];
            acc[r] = ffma2(pack2(s2.x, s2.x), w0, acc[r]);
            acc[r] = ffma2(pack2(s2.y, s2.y), w1, acc[r]);
        }
    }

    if (!POOL) {
#pragma unroll
        for (int r = 0; r < 4; r++) {
            int row = row0 + rbase + r;
            if (row < n) {
                float xv, yv; unpack2(acc[r], xv, yv);
                __half2 o = __floats2half2_rn(fmaxf(xv, 0.0f), fmaxf(yv, 0.0f));
                *(__half2*)&g_h1[(size_t)row * C + 2 * tc] = o;
            }
        }
    } else {
        int curg = -1;
        float rx = 0.0f, ry = 0.0f;
#pragma unroll
        for (int r = 0; r < 4; r++) {
            int row = row0 + rbase + r;
            if (row >= n) break;
            float xv, yv; unpack2(acc[r], xv, yv);
            xv = fmaxf(xv, 0.0f); yv = fmaxf(yv, 0.0f);
            int g = __ldg(&batch[row]);
            if (g != curg) {
                if (curg >= 0) {
                    atomicAdd(&g_psum[curg * 128 + 2 * tc], rx);
                    atomicAdd(&g_psum[curg * 128 + 2 * tc + 1], ry);
                }
                curg = g; rx = 0.0f; ry = 0.0f;
            }
            rx += xv; ry += yv;
        }
        if (curg >= 0) {
            atomicAdd(&g_psum[curg * 128 + 2 * tc], rx);
            atomicAdd(&g_psum[curg * 128 + 2 * tc + 1], ry);
        }
    }
}

// ---------------- MLP head ----------------
__global__ void k_fc(const float* __restrict__ Wf1, const float* __restrict__ bf1,
                     const float* __restrict__ Wf2, const float* __restrict__ bf2,
                     float* __restrict__ out) {
    int g = blockIdx.x;
    int t = threadIdx.x;  // 128
    __shared__ float p[128];
    __shared__ float f1[64];
    float inv = 1.0f / fmaxf(g_pcnt[g], 1.0f);
    p[t] = g_psum[g * 128 + t] * inv;
    __syncthreads();
    if (t < 64) {
        float acc = bf1[t];
#pragma unroll
        for (int k = 0; k < 128; k++) acc += p[k] * Wf1[k * 64 + t];
        f1[t] = fmaxf(acc, 0.0f);
    }
    __syncthreads();
    if (t < 10) {
        float acc = bf2[t];
#pragma unroll
        for (int k = 0; k < 64; k++) acc += f1[k] * Wf2[k * 10 + t];
        out[g * 10 + t] = acc;
    }
}

extern "C" void kernel_launch(void* const* d_in, const int* in_sizes, int n_in,
                              void* d_out, int out_size) {
    const float* x   = (const float*)d_in[0];
    const int* ei    = (const int*)d_in[1];
    const int* batch = (const int*)d_in[2];
    const float* W1  = (const float*)d_in[3];
    const float* b1  = (const float*)d_in[4];
    const float* W2  = (const float*)d_in[5];
    const float* b2  = (const float*)d_in[6];
    const float* W3  = (const float*)d_in[7];
    const float* b3  = (const float*)d_in[8];
    const float* Wf1 = (const float*)d_in[9];
    const float* bf1 = (const float*)d_in[10];
    const float* Wf2 = (const float*)d_in[11];
    const float* bf2 = (const float*)d_in[12];
    float* out = (float*)d_out;

    int N = in_sizes[0] / 3;
    int E = in_sizes[1] / 2;
    const int* src = ei;
    const int* dst = ei + E;
    int NB = (N + SCAN_B - 1) / SCAN_B;  // <= 49

    // zero + single-wave CSR builder
    k_zero<<<(N + 255) / 256, 256>>>(N);
    k_prep<<<NB, SCAN_B>>>(src, dst, batch, N, E);

    // Fused layers
    k_layer1<<<(N + 63) / 64, 256>>>(x, W1, b1, N);
    k_layer<64, 2, false><<<(N + 15) / 16, 256>>>(W2, b2, batch, N);
    k_layer<128, 4, true><<<(N + 15) / 16, 256>>>(W3, b3, batch, N);

    // Head
    k_fc<<<GRAPHS, 128>>>(Wf1, bf1, Wf2, bf2, out);
}